// round 15
// baseline (speedup 1.0000x reference)
#include <cuda_runtime.h>
#include <cstddef>

typedef unsigned long long ull;

#define N_NODES 1500
#define E_DIM   64
#define N_EDGES 24000
#define N_LOOP  10
#define WPB     8
#define NBLK    296                 // 2 blocks/SM guaranteed resident (148/152-SM parts)
#define NTHREAD (NBLK * 256)        // 75776
#define EBP     12                  // edges per warp (2000 warps x 12 = 24000)
#define NPAIR   6                   // edge pairs per warp
#define XOFF    ((size_t)N_NODES * N_NODES * E_DIM)

// ---------------- device scratch (static, allocation-free) ----------------
__device__ __align__(16) float    g_vc [N_NODES * 8];
__device__ __align__(16) float    g_goal[8];
__device__ __align__(16) float    g_y  [N_EDGES * E_DIM];
__device__ __align__(16) float    g_PA [N_NODES * E_DIM];
__device__ __align__(16) float    g_PB [N_NODES * E_DIM];
__device__ __align__(16) float    g_RA [N_NODES * E_DIM];
__device__ __align__(16) float    g_RB [N_NODES * E_DIM];
__device__ __align__(16) float    g_Pv [N_NODES * E_DIM];
__device__ __align__(16) float    g_Qv [N_NODES * E_DIM];
__device__ __align__(16) unsigned g_agg[N_NODES * E_DIM];   // zero at rest
__device__ __align__(16) float    g_Afx[E_DIM * E_DIM];
__device__ __align__(16) float    g_Bfx[E_DIM * E_DIM];
__device__ __align__(16) float    g_Cfx[E_DIM * E_DIM];
__device__ __align__(16) float    g_Afy[E_DIM * E_DIM];
__device__ __align__(16) float    g_Bfy[E_DIM * E_DIM];
__device__ __align__(16) float    g_Ahy[8 * E_DIM];
__device__ __align__(16) float    g_Bhy[8 * E_DIM];
__device__ int g_winner[N_NODES * N_NODES];
__device__ unsigned g_bar_gen;
__device__ unsigned g_bar_cnt;

// ---------------- helpers --------------------------------------------------
__device__ __forceinline__ unsigned encf(float f) {
    unsigned u = __float_as_uint(f);
    return (u & 0x80000000u) ? ~u : (u | 0x80000000u);
}
__device__ __forceinline__ float decf(unsigned e) {
    return __uint_as_float((e & 0x80000000u) ? (e & 0x7FFFFFFFu) : ~e);
}
__device__ __forceinline__ ull ffma2(ull a, ull b, ull c) {
    ull d;
    asm("fma.rn.f32x2 %0, %1, %2, %3;" : "=l"(d) : "l"(a), "l"(b), "l"(c));
    return d;
}
__device__ __forceinline__ ull packf2(float lo, float hi) {
    ull d;
    asm("mov.b64 %0, {%1, %2};" : "=l"(d) : "f"(lo), "f"(hi));
    return d;
}
__device__ __forceinline__ float2 unpackf2(ull v) {
    float2 r;
    asm("mov.b64 {%0, %1}, %2;" : "=f"(r.x), "=f"(r.y) : "l"(v));
    return r;
}

__device__ __forceinline__ void grid_barrier() {
    __threadfence();
    __syncthreads();
    if (threadIdx.x == 0) {
        unsigned gen = *(volatile unsigned*)&g_bar_gen;
        unsigned prev = atomicAdd(&g_bar_cnt, 1u);
        if (prev == NBLK - 1) {
            g_bar_cnt = 0;
            __threadfence();
            atomicAdd(&g_bar_gen, 1u);
        } else {
            while (*(volatile unsigned*)&g_bar_gen == gen) __nanosleep(32);
            __threadfence();
        }
    }
    __syncthreads();
}

// Pair-transpose a 64x64 row-major [k][j] matrix into (kp,jp) ulonglong2 tiles:
// Wp[kp*32+jp] = { (W[2kp][2jp], W[2kp+1][2jp]), (W[2kp][2jp+1], W[2kp+1][2jp+1]) }
__device__ __forceinline__ void stage_pairs(ull* dst, const float* __restrict__ W, int tid) {
    for (int idx = tid; idx < 1024; idx += 256) {
        int kp = idx >> 5, jp = idx & 31;
        const float* r0 = W + (2 * kp) * 64 + 2 * jp;
        const float* r1 = W + (2 * kp + 1) * 64 + 2 * jp;
        dst[2 * idx]     = packf2(r0[0], r1[0]);
        dst[2 * idx + 1] = packf2(r0[1], r1[1]);
    }
}

// k-pair matvec over pair-groups [G0,GN). Thread owns output cols (2l,2l+1).
// hrow[g][kp] = { h-pair of edge 2g, h-pair of edge 2g+1 } (broadcast LDS.128).
template <int G0, int GN, typename InitF, typename EmitF>
__device__ __forceinline__ void mvp(const ulonglong2* __restrict__ Wp,
                                    const ulonglong2 (&hrow)[NPAIR][32], int l,
                                    InitF init, EmitF emit) {
    constexpr int NG = GN - G0;
    ull a0[NG * 2], a1[NG * 2];
#pragma unroll
    for (int g = 0; g < NG; g++) {
#pragma unroll
        for (int i = 0; i < 2; i++) {
            float2 b = init(2 * (G0 + g) + i);
            a0[2 * g + i] = packf2(b.x, 0.f);
            a1[2 * g + i] = packf2(b.y, 0.f);
        }
    }
#pragma unroll 8
    for (int kp = 0; kp < 32; kp++) {
        ulonglong2 wq = Wp[kp * 32 + l];
#pragma unroll
        for (int g = 0; g < NG; g++) {
            ulonglong2 hv = hrow[G0 + g][kp];
            a0[2 * g]     = ffma2(wq.x, hv.x, a0[2 * g]);
            a1[2 * g]     = ffma2(wq.y, hv.x, a1[2 * g]);
            a0[2 * g + 1] = ffma2(wq.x, hv.y, a0[2 * g + 1]);
            a1[2 * g + 1] = ffma2(wq.y, hv.y, a1[2 * g + 1]);
        }
    }
#pragma unroll
    for (int g = 0; g < NG; g++) {
        float2 p0 = unpackf2(a0[2 * g]),     q0 = unpackf2(a1[2 * g]);
        float2 p1 = unpackf2(a0[2 * g + 1]), q1 = unpackf2(a1[2 * g + 1]);
        emit(G0 + g, make_float2(p0.x + p0.y, q0.x + q0.y),
                     make_float2(p1.x + p1.y, q1.x + q1.y));
    }
}

// ---------------- the persistent compute kernel ----------------------------
__global__ __launch_bounds__(256, 2) void k_all(
    float* __restrict__ out,
    const float* __restrict__ v, const float* __restrict__ labels,
    const int* __restrict__ ei,
    const float* __restrict__ hxW1, const float* __restrict__ hxb1,
    const float* __restrict__ hxW2, const float* __restrict__ hxb2,
    const float* __restrict__ hyW1, const float* __restrict__ hyb1,
    const float* __restrict__ hyW2, const float* __restrict__ hyb2,
    const float* __restrict__ fxW1, const float* __restrict__ fxb1,
    const float* __restrict__ fxW2, const float* __restrict__ fxb2,
    const float* __restrict__ fyW1, const float* __restrict__ fyb1,
    const float* __restrict__ fyW2, const float* __restrict__ fyb2)
{
    extern __shared__ __align__(16) ull dsm[];   // 3 * 2048 ull = 48 KB
    ull* W2y = dsm;          // hyW2 then fyW2 (pair-transposed)
    ull* WCx = dsm + 2048;   // Cfx
    ull* W2x = dsm + 4096;   // fxW2
    __shared__ __align__(16) ulonglong2 sH[WPB][NPAIR][32];   // 24 KB
    __shared__ float sB[6][64];   // 0:hyb1 1:hyb2 2:fyb1 3:fyb2 4:fxb1 5:fxb2

    int tid = threadIdx.x, w = tid >> 5, l = tid & 31;
    int gt = blockIdx.x * 256 + tid;
    int wgid = blockIdx.x * WPB + w;

    // ================= P0: inputs -> scratch =================
    if (gt < N_NODES) {
        float row[8];
#pragma unroll
        for (int c = 0; c < 7; c++) row[c] = v[gt * 7 + c];
        row[7] = labels[gt];
#pragma unroll
        for (int c = 0; c < 8; c++) g_vc[gt * 8 + c] = row[c];
        if (row[7] > 0.5f) {
#pragma unroll
            for (int c = 0; c < 8; c++) g_goal[c] = row[c];
        }
    }
    if (gt < 4096) {
        float a = fxW1[gt];
        g_Afx[gt] = a + fxW1[4096 + gt];
        g_Bfx[gt] = fxW1[8192 + gt] - a;
        g_Cfx[gt] = fxW1[12288 + gt];
        float b = fyW1[gt];
        g_Afy[gt] = b + fyW1[4096 + gt];
        g_Bfy[gt] = fyW1[8192 + gt] - b;
    }
    if (gt < 512) {
        float c = hyW1[gt];
        g_Ahy[gt] = c + hyW1[512 + gt];
        g_Bhy[gt] = hyW1[1024 + gt] - c;
    }
    for (int i = gt; i < N_NODES * N_NODES; i += NTHREAD) g_winner[i] = -1;
    grid_barrier();

    // ================= P1: derived state =================
    if (gt < N_EDGES)
        atomicMax(&g_winner[ei[gt] * N_NODES + ei[N_EDGES + gt]], gt);
    for (int i = gt; i < N_NODES * E_DIM; i += NTHREAD) {
        int nn = i >> 6, j = i & 63;
        float s = 0.f, q = 0.f;
#pragma unroll
        for (int k = 0; k < 8; k++) {
            float vk = g_vc[nn * 8 + k];
            s += vk * g_Ahy[k * 64 + j];
            q += vk * g_Bhy[k * 64 + j];
        }
        __stcg(&g_Pv[i], s);
        __stcg(&g_Qv[i], q);
    }
    stage_pairs(W2y, hyW2, tid);
    stage_pairs(WCx, g_Cfx, tid);
    stage_pairs(W2x, fxW2, tid);
    if (tid < 64) {
        sB[0][tid] = hyb1[tid]; sB[1][tid] = hyb2[tid];
        sB[2][tid] = fyb1[tid]; sB[3][tid] = fyb2[tid];
        sB[4][tid] = fxb1[tid]; sB[5][tid] = fxb2[tid];
    }

    // hx: per node-warp, result kept in registers
    int n = wgid;
    bool has_node = (n < N_NODES);
    float2 xv = make_float2(0.f, 0.f);
    if (has_node) {
        float* xs = (float*)&sH[w][0][0];   // 64 floats scratch
        float* hs = xs + 64;
        {
            int g = l >> 3, r = l & 7;
            float vcv = g_vc[n * 8 + r];
            float gv  = g_goal[r];
            float dd  = vcv - gv;
            xs[l] = (g == 0) ? vcv : (g == 1) ? gv : (g == 2) ? dd : dd * dd;
        }
        __syncwarp();
        float2 acc = __ldg((const float2*)hxb1 + l);
#pragma unroll 8
        for (int k = 0; k < 32; k++) {
            float vk  = xs[k];
            float2 wv = __ldg((const float2*)hxW1 + k * 32 + l);
            acc.x += vk * wv.x; acc.y += vk * wv.y;
        }
        acc.x = fmaxf(acc.x, 0.f); acc.y = fmaxf(acc.y, 0.f);
        ((float2*)hs)[l] = acc;
        __syncwarp();
        float2 o = __ldg((const float2*)hxb2 + l);
#pragma unroll 8
        for (int k = 0; k < 64; k++) {
            float hk  = hs[k];
            float2 wv = __ldg((const float2*)hxW2 + k * 32 + l);
            o.x += hk * wv.x; o.y += hk * wv.y;
        }
        xv = o;
        __syncwarp();
    }

    // edge ownership (registers for the whole kernel)
    int ebase = wgid * EBP;
    int ec = N_EDGES - ebase;
    if (ec > EBP) ec = EBP;
    if (ec < 0) ec = 0;
    int src[EBP], tgt[EBP];
#pragma unroll
    for (int e = 0; e < EBP; e++) {
        int eg = (e < ec) ? (ebase + e) : 0;
        src[e] = __ldg(ei + eg);
        tgt[e] = __ldg(ei + N_EDGES + eg);
    }
    float2 yv[EBP];

    const float2* PA2 = (const float2*)g_PA;
    const float2* PB2 = (const float2*)g_PB;
    const float2* RA2 = (const float2*)g_RA;
    const float2* RB2 = (const float2*)g_RB;
    const float2* Pv2 = (const float2*)g_Pv;
    const float2* Qv2 = (const float2*)g_Qv;
    const float2* Afx2 = (const float2*)g_Afx;
    const float2* Bfx2 = (const float2*)g_Bfx;
    const float2* Afy2 = (const float2*)g_Afy;
    const float2* Bfy2 = (const float2*)g_Bfy;

    grid_barrier();

    // ================= main loop =================
    for (int t = 0; t <= N_LOOP; t++) {
        // ---- node phase ----
        if (t == 1) stage_pairs(W2y, fyW2, tid);   // swap hyW2 -> fyW2
        if (has_node) {
            if (t > 0) {
                unsigned a0 = atomicExch(&g_agg[n * 64 + 2 * l], 0u);
                unsigned a1 = atomicExch(&g_agg[n * 64 + 2 * l + 1], 0u);
                xv.x = fmaxf(xv.x, a0 ? decf(a0) : 0.f);
                xv.y = fmaxf(xv.y, a1 ? decf(a1) : 0.f);
            }
            float* xs = (float*)&sH[w][0][0];
            ((float2*)xs)[l] = xv;
            __syncwarp();
            float2 aA = make_float2(0.f, 0.f), aB = aA, aC = aA, aD = aA;
#pragma unroll 8
            for (int k = 0; k < 64; k++) {
                float xk = xs[k];
                float2 wa = __ldg(Afx2 + k * 32 + l);
                float2 wb = __ldg(Bfx2 + k * 32 + l);
                float2 wc = __ldg(Afy2 + k * 32 + l);
                float2 wd = __ldg(Bfy2 + k * 32 + l);
                aA.x += xk * wa.x; aA.y += xk * wa.y;
                aB.x += xk * wb.x; aB.y += xk * wb.y;
                aC.x += xk * wc.x; aC.y += xk * wc.y;
                aD.x += xk * wd.x; aD.y += xk * wd.y;
            }
            __stcg((float2*)g_PA + n * 32 + l, aA);
            __stcg((float2*)g_PB + n * 32 + l, aB);
            __stcg((float2*)g_RA + n * 32 + l, aC);
            __stcg((float2*)g_RB + n * 32 + l, aD);
            if (t == N_LOOP)   // emit x into output tail (outside memset region)
                *(float2*)(out + XOFF + (size_t)n * 64 + 2 * l) = xv;
            __syncwarp();
        }
        grid_barrier();

        // ---- edge phase ----
        // layer 1 of hy (t==0) / fy: relu hidden pairs, 2 edges per STS.128
        {
            float2 b1 = ((const float2*)sB[(t == 0) ? 0 : 2])[l];
            const float2* Tm = (t == 0) ? Pv2 : RA2;
            const float2* Sm = (t == 0) ? Qv2 : RB2;
#pragma unroll
            for (int g = 0; g < NPAIR; g++) {
                ulonglong2 hv;
#pragma unroll
                for (int i = 0; i < 2; i++) {
                    int e = 2 * g + i;
                    float2 a = __ldcg(Tm + tgt[e] * 32 + l);
                    float2 b = __ldcg(Sm + src[e] * 32 + l);
                    ull p = packf2(fmaxf(a.x + b.x + b1.x, 0.f),
                                   fmaxf(a.y + b.y + b1.y, 0.f));
                    if (i == 0) hv.x = p; else hv.y = p;
                }
                sH[w][g][l] = hv;
            }
        }
        __syncwarp();

        // layer 2 of hy/fy -> yv
        {
            float2 b2 = ((const float2*)sB[(t == 0) ? 1 : 3])[l];
            const ulonglong2* Wp = (const ulonglong2*)W2y;
            auto init = [&](int) { return b2; };
            auto emit = [&](int g, float2 r0, float2 r1) {
                int e0 = 2 * g, e1 = 2 * g + 1;
                if (t == 0) { yv[e0] = r0; yv[e1] = r1; }
                else {
                    yv[e0].x = fmaxf(yv[e0].x, r0.x); yv[e0].y = fmaxf(yv[e0].y, r0.y);
                    yv[e1].x = fmaxf(yv[e1].x, r1.x); yv[e1].y = fmaxf(yv[e1].y, r1.y);
                }
            };
            mvp<0, 3>(Wp, sH[w], l, init, emit);
            mvp<3, NPAIR>(Wp, sH[w], l, init, emit);
        }

        if (t == N_LOOP) {
            // final y -> global (scatter kernel consumes after memset join)
#pragma unroll
            for (int e = 0; e < EBP; e++)
                if (e < ec)
                    __stcg((float2*)g_y + (size_t)(ebase + e) * 32 + l, yv[e]);
            break;
        }

        // stage y for fx layer 1
        __syncwarp();
#pragma unroll
        for (int g = 0; g < NPAIR; g++) {
            ulonglong2 hv;
            hv.x = packf2(yv[2 * g].x,     yv[2 * g].y);
            hv.y = packf2(yv[2 * g + 1].x, yv[2 * g + 1].y);
            sH[w][g][l] = hv;
        }
        __syncwarp();

        // fx layer 1: PA[src] + PB[tgt] + b1 + y @ Cfx, relu -> restage
        {
            float2 b1x = ((const float2*)sB[4])[l];
            const ulonglong2* Wp = (const ulonglong2*)WCx;
            auto init = [&](int e) {
                float2 pa = __ldcg(PA2 + src[e] * 32 + l);
                float2 pb = __ldcg(PB2 + tgt[e] * 32 + l);
                return make_float2(pa.x + pb.x + b1x.x, pa.y + pb.y + b1x.y);
            };
            auto emit = [&](int g, float2 r0, float2 r1) {
                ulonglong2 hv;
                hv.x = packf2(fmaxf(r0.x, 0.f), fmaxf(r0.y, 0.f));
                hv.y = packf2(fmaxf(r1.x, 0.f), fmaxf(r1.y, 0.f));
                sH[w][g][l] = hv;
            };
            mvp<0, 3>(Wp, sH[w], l, init, emit);
            mvp<3, NPAIR>(Wp, sH[w], l, init, emit);
        }
        __syncwarp();

        // fx layer 2 + atomic max scatter into agg
        {
            float2 b2x = ((const float2*)sB[5])[l];
            const ulonglong2* Wp = (const ulonglong2*)W2x;
            auto init = [&](int) { return b2x; };
            auto emit = [&](int g, float2 r0, float2 r1) {
#pragma unroll
                for (int i = 0; i < 2; i++) {
                    int e = 2 * g + i;
                    float2 r = (i == 0) ? r0 : r1;
                    if (e < ec) {
                        unsigned* ap = g_agg + tgt[e] * 64 + 2 * l;
                        atomicMax(ap,     encf(r.x));
                        atomicMax(ap + 1, encf(r.y));
                    }
                }
            };
            mvp<0, 3>(Wp, sH[w], l, init, emit);
            mvp<3, NPAIR>(Wp, sH[w], l, init, emit);
        }
        grid_barrier();
    }
}

// ---------------- final scatter (after memset join) ------------------------
__global__ void k_scatter(float* __restrict__ out, const int* __restrict__ ei) {
    int tid = threadIdx.x, w = tid >> 5, l = tid & 31;
    int e = blockIdx.x * WPB + w;
    if (e >= N_EDGES) return;
    int key = ei[e] * N_NODES + ei[N_EDGES + e];
    if (__ldg(&g_winner[key]) == e)
        ((float2*)out)[(size_t)key * 32 + l] = ((const float2*)g_y)[(size_t)e * 32 + l];
}

// ---------------- launch ---------------------------------------------------
extern "C" void kernel_launch(void* const* d_in, const int* in_sizes, int n_in,
                              void* d_out, int out_size) {
    const float* v      = (const float*)d_in[0];
    const float* labels = (const float*)d_in[1];
    const int*   ei     = (const int*)  d_in[4];
    const float* hxW1 = (const float*)d_in[6];
    const float* hxb1 = (const float*)d_in[7];
    const float* hxW2 = (const float*)d_in[8];
    const float* hxb2 = (const float*)d_in[9];
    const float* hyW1 = (const float*)d_in[10];
    const float* hyb1 = (const float*)d_in[11];
    const float* hyW2 = (const float*)d_in[12];
    const float* hyb2 = (const float*)d_in[13];
    const float* fxW1 = (const float*)d_in[14];
    const float* fxb1 = (const float*)d_in[15];
    const float* fxW2 = (const float*)d_in[16];
    const float* fxb2 = (const float*)d_in[17];
    const float* fyW1 = (const float*)d_in[18];
    const float* fyb1 = (const float*)d_in[19];
    const float* fyW2 = (const float*)d_in[20];
    const float* fyb2 = (const float*)d_in[21];
    float* out = (float*)d_out;

    const int DSM = 3 * 2048 * (int)sizeof(ull);   // 48 KB dynamic
    static cudaStream_t s2 = nullptr;
    static cudaEvent_t ev_fork = nullptr, ev_join = nullptr;
    static bool attr_set = false;
    if (!s2) {
        cudaStreamCreate(&s2);
        cudaEventCreateWithFlags(&ev_fork, cudaEventDisableTiming);
        cudaEventCreateWithFlags(&ev_join, cudaEventDisableTiming);
    }
    if (!attr_set) {
        cudaFuncSetAttribute(k_all, cudaFuncAttributeMaxDynamicSharedMemorySize, DSM);
        attr_set = true;
    }

    // fork: driver memset fills the 576MB edge_feat region concurrently
    cudaEventRecord(ev_fork, 0);
    cudaStreamWaitEvent(s2, ev_fork, 0);
    cudaMemsetAsync(out, 0, XOFF * sizeof(float), s2);
    cudaEventRecord(ev_join, s2);

    // main stream: the whole GNN
    k_all<<<NBLK, 256, DSM>>>(out, v, labels, ei,
                              hxW1, hxb1, hxW2, hxb2,
                              hyW1, hyb1, hyW2, hyb2,
                              fxW1, fxb1, fxW2, fxb2,
                              fyW1, fyb1, fyW2, fyb2);

    // join memset, then sparse scatter of winner rows
    cudaStreamWaitEvent(0, ev_join, 0);
    k_scatter<<<(N_EDGES + WPB - 1) / WPB, 256>>>(out, ei);
}

// round 16
// speedup vs baseline: 1.1612x; 1.1612x over previous
#include <cuda_runtime.h>
#include <cstddef>

typedef unsigned long long ull;

#define N_NODES 1500
#define E_DIM   64
#define N_EDGES 24000
#define N_LOOP  10
#define BLKT    384                 // threads per block (12 warps)
#define WPB     12
#define NBLK    296                 // 2 blocks/SM guaranteed resident
#define NTHREAD (NBLK * BLKT)       // 113664
#define NWARPS  (NBLK * WPB)        // 3552
#define EBP     7                   // edges per warp (3552*7 = 24864 >= 24000)
#define ZSTRIDE NTHREAD
#define ZTOT    36000000u           // 1500*1500*64 / 4 float4s (edge_feat region)
#define XOFF    ((size_t)N_NODES * N_NODES * E_DIM)

// ---------------- device scratch (static, allocation-free) ----------------
__device__ __align__(16) float    g_vc [N_NODES * 8];
__device__ __align__(16) float    g_goal[8];
__device__ __align__(16) float    g_PA [N_NODES * E_DIM];
__device__ __align__(16) float    g_PB [N_NODES * E_DIM];
__device__ __align__(16) float    g_RA [N_NODES * E_DIM];
__device__ __align__(16) float    g_RB [N_NODES * E_DIM];
__device__ __align__(16) float    g_Pv [N_NODES * E_DIM];
__device__ __align__(16) float    g_Qv [N_NODES * E_DIM];
__device__ __align__(16) unsigned g_agg[N_NODES * E_DIM];   // zero at rest
__device__ __align__(16) float    g_Afx[E_DIM * E_DIM];
__device__ __align__(16) float    g_Bfx[E_DIM * E_DIM];
__device__ __align__(16) float    g_Cfx[E_DIM * E_DIM];
__device__ __align__(16) float    g_Afy[E_DIM * E_DIM];
__device__ __align__(16) float    g_Bfy[E_DIM * E_DIM];
__device__ __align__(16) float    g_Ahy[8 * E_DIM];
__device__ __align__(16) float    g_Bhy[8 * E_DIM];
__device__ int g_winner[N_NODES * N_NODES];
__device__ unsigned g_bar_gen;
__device__ unsigned g_bar_cnt;

// ---------------- helpers --------------------------------------------------
__device__ __forceinline__ unsigned encf(float f) {
    unsigned u = __float_as_uint(f);
    return (u & 0x80000000u) ? ~u : (u | 0x80000000u);
}
__device__ __forceinline__ float decf(unsigned e) {
    return __uint_as_float((e & 0x80000000u) ? (e & 0x7FFFFFFFu) : ~e);
}
__device__ __forceinline__ ull ffma2(ull a, ull b, ull c) {
    ull d;
    asm("fma.rn.f32x2 %0, %1, %2, %3;" : "=l"(d) : "l"(a), "l"(b), "l"(c));
    return d;
}
__device__ __forceinline__ ull packf2(float lo, float hi) {
    ull d;
    asm("mov.b64 %0, {%1, %2};" : "=l"(d) : "f"(lo), "f"(hi));
    return d;
}
__device__ __forceinline__ float2 unpackf2(ull v) {
    float2 r;
    asm("mov.b64 {%0, %1}, %2;" : "=f"(r.x), "=f"(r.y) : "l"(v));
    return r;
}

__device__ __forceinline__ void grid_barrier() {
    __threadfence();
    __syncthreads();
    if (threadIdx.x == 0) {
        unsigned gen = *(volatile unsigned*)&g_bar_gen;
        unsigned prev = atomicAdd(&g_bar_cnt, 1u);
        if (prev == NBLK - 1) {
            g_bar_cnt = 0;
            __threadfence();
            atomicAdd(&g_bar_gen, 1u);
        } else {
            while (*(volatile unsigned*)&g_bar_gen == gen) __nanosleep(32);
            __threadfence();
        }
    }
    __syncthreads();
}

// Pair-transpose a 64x64 row-major [k][j] matrix into (kp,jp) ulonglong2 tiles:
// Wp[kp*32+jp] = { (W[2kp][2jp], W[2kp+1][2jp]), (W[2kp][2jp+1], W[2kp+1][2jp+1]) }
__device__ __forceinline__ void stage_pairs(ull* dst, const float* __restrict__ W, int tid) {
    for (int idx = tid; idx < 1024; idx += BLKT) {
        int kp = idx >> 5, jp = idx & 31;
        const float* r0 = W + (2 * kp) * 64 + 2 * jp;
        const float* r1 = W + (2 * kp + 1) * 64 + 2 * jp;
        dst[2 * idx]     = packf2(r0[0], r1[0]);
        dst[2 * idx + 1] = packf2(r0[1], r1[1]);
    }
}

// k-pair matvec over all EBP edges in one pass (weights loaded once).
// hrow[e][kp] = (h[2kp], h[2kp+1]) of edge e, broadcast LDS.64.
// Thread owns output columns (2l, 2l+1); a0/a1 hold their even/odd-k partials.
template <typename InitF, typename EmitF>
__device__ __forceinline__ void mv(const ulonglong2* __restrict__ Wp,
                                   const ull (&hrow)[EBP][32], int l,
                                   InitF init, EmitF emit) {
    ull a0[EBP], a1[EBP];
#pragma unroll
    for (int e = 0; e < EBP; e++) {
        float2 b = init(e);
        a0[e] = packf2(b.x, 0.f);
        a1[e] = packf2(b.y, 0.f);
    }
#pragma unroll 8
    for (int kp = 0; kp < 32; kp++) {
        ulonglong2 wq = Wp[kp * 32 + l];
#pragma unroll
        for (int e = 0; e < EBP; e++) {
            ull hv = hrow[e][kp];
            a0[e] = ffma2(wq.x, hv, a0[e]);
            a1[e] = ffma2(wq.y, hv, a1[e]);
        }
    }
#pragma unroll
    for (int e = 0; e < EBP; e++) {
        float2 p = unpackf2(a0[e]), q = unpackf2(a1[e]);
        emit(e, make_float2(p.x + p.y, q.x + q.y));
    }
}

#define ZBURST()                                                          \
    {                                                                     \
        _Pragma("unroll") for (int j_ = 0; j_ < 8; j_++) {                \
            if (zi < ZTOT) __stcs(out4 + zi, z4);                         \
            zi += ZSTRIDE;                                                \
        }                                                                 \
    }

// ---------------- the single mega-kernel ----------------------------------
__global__ __launch_bounds__(BLKT, 2) void k_all(
    float* __restrict__ out,
    const float* __restrict__ v, const float* __restrict__ labels,
    const int* __restrict__ ei,
    const float* __restrict__ hxW1, const float* __restrict__ hxb1,
    const float* __restrict__ hxW2, const float* __restrict__ hxb2,
    const float* __restrict__ hyW1, const float* __restrict__ hyb1,
    const float* __restrict__ hyW2, const float* __restrict__ hyb2,
    const float* __restrict__ fxW1, const float* __restrict__ fxb1,
    const float* __restrict__ fxW2, const float* __restrict__ fxb2,
    const float* __restrict__ fyW1, const float* __restrict__ fyb1,
    const float* __restrict__ fyW2, const float* __restrict__ fyb2)
{
    extern __shared__ __align__(16) ull dsm[];   // 3 * 2048 ull = 48 KB
    ull* W2y = dsm;          // hyW2 then fyW2 (pair-transposed)
    ull* WCx = dsm + 2048;   // Cfx
    ull* W2x = dsm + 4096;   // fxW2
    __shared__ __align__(16) ull sH[WPB][EBP][32];   // 21 KB
    __shared__ float sB[6][64];   // 0:hyb1 1:hyb2 2:fyb1 3:fyb2 4:fxb1 5:fxb2

    int tid = threadIdx.x, w = tid >> 5, l = tid & 31;
    int gt = blockIdx.x * BLKT + tid;
    int wgid = blockIdx.x * WPB + w;
    float4* out4 = (float4*)out;
    const float4 z4 = make_float4(0.f, 0.f, 0.f, 0.f);
    unsigned zi = (unsigned)gt;

    // ================= P0: inputs -> scratch =================
    if (gt < N_NODES) {
        float row[8];
#pragma unroll
        for (int c = 0; c < 7; c++) row[c] = v[gt * 7 + c];
        row[7] = labels[gt];
#pragma unroll
        for (int c = 0; c < 8; c++) g_vc[gt * 8 + c] = row[c];
        if (row[7] > 0.5f) {
#pragma unroll
            for (int c = 0; c < 8; c++) g_goal[c] = row[c];
        }
    }
    if (gt < 4096) {
        float a = fxW1[gt];
        g_Afx[gt] = a + fxW1[4096 + gt];
        g_Bfx[gt] = fxW1[8192 + gt] - a;
        g_Cfx[gt] = fxW1[12288 + gt];
        float b = fyW1[gt];
        g_Afy[gt] = b + fyW1[4096 + gt];
        g_Bfy[gt] = fyW1[8192 + gt] - b;
    }
    if (gt < 512) {
        float c = hyW1[gt];
        g_Ahy[gt] = c + hyW1[512 + gt];
        g_Bhy[gt] = hyW1[1024 + gt] - c;
    }
    for (int i = gt; i < N_NODES * N_NODES; i += NTHREAD) g_winner[i] = -1;
    grid_barrier();

    // ================= P1: derived state =================
    if (gt < N_EDGES)
        atomicMax(&g_winner[ei[gt] * N_NODES + ei[N_EDGES + gt]], gt);
    for (int i = gt; i < N_NODES * E_DIM; i += NTHREAD) {
        int nn = i >> 6, j = i & 63;
        float s = 0.f, q = 0.f;
#pragma unroll
        for (int k = 0; k < 8; k++) {
            float vk = g_vc[nn * 8 + k];
            s += vk * g_Ahy[k * 64 + j];
            q += vk * g_Bhy[k * 64 + j];
        }
        __stcg(&g_Pv[i], s);
        __stcg(&g_Qv[i], q);
    }
    stage_pairs(W2y, hyW2, tid);
    stage_pairs(WCx, g_Cfx, tid);
    stage_pairs(W2x, fxW2, tid);
    if (tid < 64) {
        sB[0][tid] = hyb1[tid]; sB[1][tid] = hyb2[tid];
        sB[2][tid] = fyb1[tid]; sB[3][tid] = fyb2[tid];
        sB[4][tid] = fxb1[tid]; sB[5][tid] = fxb2[tid];
    }

    // hx: per node-warp, result kept in registers
    int n = wgid;
    bool has_node = (n < N_NODES);
    float2 xv = make_float2(0.f, 0.f);
    if (has_node) {
        float* xs = (float*)&sH[w][0][0];   // 64+64 floats scratch in warp's region
        float* hs = xs + 64;
        {
            int g = l >> 3, r = l & 7;
            float vcv = g_vc[n * 8 + r];
            float gv  = g_goal[r];
            float dd  = vcv - gv;
            xs[l] = (g == 0) ? vcv : (g == 1) ? gv : (g == 2) ? dd : dd * dd;
        }
        __syncwarp();
        float2 acc = __ldg((const float2*)hxb1 + l);
#pragma unroll 4
        for (int k = 0; k < 32; k++) {
            float vk  = xs[k];
            float2 wv = __ldg((const float2*)hxW1 + k * 32 + l);
            acc.x += vk * wv.x; acc.y += vk * wv.y;
        }
        acc.x = fmaxf(acc.x, 0.f); acc.y = fmaxf(acc.y, 0.f);
        ((float2*)hs)[l] = acc;
        __syncwarp();
        float2 o = __ldg((const float2*)hxb2 + l);
#pragma unroll 4
        for (int k = 0; k < 64; k++) {
            float hk  = hs[k];
            float2 wv = __ldg((const float2*)hxW2 + k * 32 + l);
            o.x += hk * wv.x; o.y += hk * wv.y;
        }
        xv = o;
        __syncwarp();
    }

    // edge ownership (registers for the whole kernel)
    int ebase = wgid * EBP;
    int ec = N_EDGES - ebase;
    if (ec > EBP) ec = EBP;
    if (ec < 0) ec = 0;
    int src[EBP], tgt[EBP];
#pragma unroll
    for (int e = 0; e < EBP; e++) {
        int eg = (e < ec) ? (ebase + e) : 0;
        src[e] = __ldg(ei + eg);
        tgt[e] = __ldg(ei + N_EDGES + eg);
    }
    float2 yv[EBP];

    const float2* PA2 = (const float2*)g_PA;
    const float2* PB2 = (const float2*)g_PB;
    const float2* RA2 = (const float2*)g_RA;
    const float2* RB2 = (const float2*)g_RB;
    const float2* Pv2 = (const float2*)g_Pv;
    const float2* Qv2 = (const float2*)g_Qv;
    const float2* Afx2 = (const float2*)g_Afx;
    const float2* Bfx2 = (const float2*)g_Bfx;
    const float2* Afy2 = (const float2*)g_Afy;
    const float2* Bfy2 = (const float2*)g_Bfy;

    grid_barrier();

    // ================= main loop =================
    for (int t = 0; t <= N_LOOP; t++) {
        // ---- node phase ----
        if (t == 1) stage_pairs(W2y, fyW2, tid);   // swap hyW2 -> fyW2
        if (has_node) {
            if (t > 0) {
                unsigned a0 = atomicExch(&g_agg[n * 64 + 2 * l], 0u);
                unsigned a1 = atomicExch(&g_agg[n * 64 + 2 * l + 1], 0u);
                xv.x = fmaxf(xv.x, a0 ? decf(a0) : 0.f);
                xv.y = fmaxf(xv.y, a1 ? decf(a1) : 0.f);
            }
            float* xs = (float*)&sH[w][0][0];
            ((float2*)xs)[l] = xv;
            __syncwarp();
            float2 aA = make_float2(0.f, 0.f), aB = aA, aC = aA, aD = aA;
#pragma unroll 4
            for (int k = 0; k < 64; k++) {
                float xk = xs[k];
                float2 wa = __ldg(Afx2 + k * 32 + l);
                float2 wb = __ldg(Bfx2 + k * 32 + l);
                float2 wc = __ldg(Afy2 + k * 32 + l);
                float2 wd = __ldg(Bfy2 + k * 32 + l);
                aA.x += xk * wa.x; aA.y += xk * wa.y;
                aB.x += xk * wb.x; aB.y += xk * wb.y;
                aC.x += xk * wc.x; aC.y += xk * wc.y;
                aD.x += xk * wd.x; aD.y += xk * wd.y;
            }
            __stcg((float2*)g_PA + n * 32 + l, aA);
            __stcg((float2*)g_PB + n * 32 + l, aB);
            __stcg((float2*)g_RA + n * 32 + l, aC);
            __stcg((float2*)g_RB + n * 32 + l, aD);
            if (t == N_LOOP)   // emit x into output tail straight from registers
                *(float2*)(out + XOFF + (size_t)n * 64 + 2 * l) = xv;
            __syncwarp();
        }
        grid_barrier();

        // ---- edge phase ----
        // layer 1 of hy (t==0) / fy: relu hidden pairs, lane l stages kp=l
        {
            float2 b1 = ((const float2*)sB[(t == 0) ? 0 : 2])[l];
            const float2* Tm = (t == 0) ? Pv2 : RA2;
            const float2* Sm = (t == 0) ? Qv2 : RB2;
#pragma unroll
            for (int e = 0; e < EBP; e++) {
                float2 a = __ldcg(Tm + tgt[e] * 32 + l);
                float2 b = __ldcg(Sm + src[e] * 32 + l);
                sH[w][e][l] = packf2(fmaxf(a.x + b.x + b1.x, 0.f),
                                     fmaxf(a.y + b.y + b1.y, 0.f));
            }
        }
        __syncwarp();
        ZBURST();

        // layer 2 of hy/fy -> yv
        {
            float2 b2 = ((const float2*)sB[(t == 0) ? 1 : 3])[l];
            mv((const ulonglong2*)W2y, sH[w], l,
               [&](int) { return b2; },
               [&](int e, float2 r) {
                   if (t == 0) yv[e] = r;
                   else { yv[e].x = fmaxf(yv[e].x, r.x); yv[e].y = fmaxf(yv[e].y, r.y); }
               });
        }
        ZBURST();

        if (t == N_LOOP) {
            // scatter winner rows straight from registers (zero-fill done @ t==9)
#pragma unroll
            for (int e = 0; e < EBP; e++) {
                if (e < ec) {
                    int key = src[e] * N_NODES + tgt[e];
                    if (__ldg(&g_winner[key]) == ebase + e)
                        __stcs((float2*)out + (size_t)key * 32 + l, yv[e]);
                }
            }
            break;
        }

        // stage y for fx layer 1
        __syncwarp();
#pragma unroll
        for (int e = 0; e < EBP; e++) sH[w][e][l] = packf2(yv[e].x, yv[e].y);
        __syncwarp();

        // fx layer 1: PA[src] + PB[tgt] + b1 + y @ Cfx, relu -> restage
        {
            float2 b1x = ((const float2*)sB[4])[l];
            mv((const ulonglong2*)WCx, sH[w], l,
               [&](int e) {
                   float2 pa = __ldcg(PA2 + src[e] * 32 + l);
                   float2 pb = __ldcg(PB2 + tgt[e] * 32 + l);
                   return make_float2(pa.x + pb.x + b1x.x, pa.y + pb.y + b1x.y);
               },
               [&](int e, float2 r) {
                   sH[w][e][l] = packf2(fmaxf(r.x, 0.f), fmaxf(r.y, 0.f));
               });
        }
        __syncwarp();
        ZBURST();

        // fx layer 2 + atomic max scatter into agg
        {
            float2 b2x = ((const float2*)sB[5])[l];
            mv((const ulonglong2*)W2x, sH[w], l,
               [&](int) { return b2x; },
               [&](int e, float2 r) {
                   if (e < ec) {
                       unsigned* ap = g_agg + tgt[e] * 64 + 2 * l;
                       atomicMax(ap,     encf(r.x));
                       atomicMax(ap + 1, encf(r.y));
                   }
               });
        }
        ZBURST();

        if (t == N_LOOP - 1) {   // guarantee edge_feat zero-fill complete before scatter
            while (zi < ZTOT) { __stcs(out4 + zi, z4); zi += ZSTRIDE; }
        }
        grid_barrier();
    }
}

// ---------------- launch ---------------------------------------------------
extern "C" void kernel_launch(void* const* d_in, const int* in_sizes, int n_in,
                              void* d_out, int out_size) {
    const float* v      = (const float*)d_in[0];
    const float* labels = (const float*)d_in[1];
    const int*   ei     = (const int*)  d_in[4];
    const float* hxW1 = (const float*)d_in[6];
    const float* hxb1 = (const float*)d_in[7];
    const float* hxW2 = (const float*)d_in[8];
    const float* hxb2 = (const float*)d_in[9];
    const float* hyW1 = (const float*)d_in[10];
    const float* hyb1 = (const float*)d_in[11];
    const float* hyW2 = (const float*)d_in[12];
    const float* hyb2 = (const float*)d_in[13];
    const float* fxW1 = (const float*)d_in[14];
    const float* fxb1 = (const float*)d_in[15];
    const float* fxW2 = (const float*)d_in[16];
    const float* fxb2 = (const float*)d_in[17];
    const float* fyW1 = (const float*)d_in[18];
    const float* fyb1 = (const float*)d_in[19];
    const float* fyW2 = (const float*)d_in[20];
    const float* fyb2 = (const float*)d_in[21];
    float* out = (float*)d_out;

    const int DSM = 3 * 2048 * (int)sizeof(ull);   // 48 KB dynamic
    static bool attr_set = false;
    if (!attr_set) {
        cudaFuncSetAttribute(k_all, cudaFuncAttributeMaxDynamicSharedMemorySize, DSM);
        attr_set = true;
    }

    k_all<<<NBLK, BLKT, DSM>>>(out, v, labels, ei,
                               hxW1, hxb1, hxW2, hxb2,
                               hyW1, hyb1, hyW2, hyb2,
                               fxW1, fxb1, fxW2, fxb2,
                               fyW1, fyb1, fyW2, fyb2);
}

// round 17
// speedup vs baseline: 1.2490x; 1.0756x over previous
#include <cuda_runtime.h>
#include <cstddef>

typedef unsigned long long ull;

#define N_NODES 1500
#define E_DIM   64
#define N_EDGES 24000
#define N_LOOP  10
#define BLKT    384                 // threads per block (12 warps)
#define WPB     12
#define NBLK    296                 // 2 blocks/SM guaranteed resident
#define NTHREAD (NBLK * BLKT)       // 113664
#define NWARPS  (NBLK * WPB)        // 3552
#define EBP     7                   // edges per warp (3552*7 = 24864 >= 24000)
#define NAGG    (N_NODES * E_DIM)
#define ZSTRIDE NTHREAD
#define ZTOT    36000000u           // 1500*1500*64 / 4 float4s (edge_feat region)
#define XOFF    ((size_t)N_NODES * N_NODES * E_DIM)

// ---------------- device scratch (static, allocation-free) ----------------
__device__ __align__(16) float    g_vc [N_NODES * 8];
__device__ __align__(16) float    g_goal[8];
__device__ __align__(16) float    g_PA [N_NODES * E_DIM];
__device__ __align__(16) float    g_PB [N_NODES * E_DIM];
__device__ __align__(16) float    g_RA [N_NODES * E_DIM];
__device__ __align__(16) float    g_RB [N_NODES * E_DIM];
__device__ __align__(16) float    g_Pv [N_NODES * E_DIM];
__device__ __align__(16) float    g_Qv [N_NODES * E_DIM];
__device__ __align__(16) unsigned g_agg[2 * NAGG];          // ping-pong, zero-at-need
__device__ __align__(16) float    g_Afx[E_DIM * E_DIM];
__device__ __align__(16) float    g_Bfx[E_DIM * E_DIM];
__device__ __align__(16) float    g_Cfx[E_DIM * E_DIM];
__device__ __align__(16) float    g_Afy[E_DIM * E_DIM];
__device__ __align__(16) float    g_Bfy[E_DIM * E_DIM];
__device__ __align__(16) float    g_Ahy[8 * E_DIM];
__device__ __align__(16) float    g_Bhy[8 * E_DIM];
__device__ int g_winner[N_NODES * N_NODES];
__device__ unsigned g_bar_gen;
__device__ unsigned g_bar_cnt;

// ---------------- helpers --------------------------------------------------
__device__ __forceinline__ unsigned encf(float f) {
    unsigned u = __float_as_uint(f);
    return (u & 0x80000000u) ? ~u : (u | 0x80000000u);
}
__device__ __forceinline__ float decf(unsigned e) {
    return __uint_as_float((e & 0x80000000u) ? (e & 0x7FFFFFFFu) : ~e);
}
__device__ __forceinline__ ull ffma2(ull a, ull b, ull c) {
    ull d;
    asm("fma.rn.f32x2 %0, %1, %2, %3;" : "=l"(d) : "l"(a), "l"(b), "l"(c));
    return d;
}
__device__ __forceinline__ ull packf2(float lo, float hi) {
    ull d;
    asm("mov.b64 %0, {%1, %2};" : "=l"(d) : "f"(lo), "f"(hi));
    return d;
}
__device__ __forceinline__ float2 unpackf2(ull v) {
    float2 r;
    asm("mov.b64 {%0, %1}, %2;" : "=f"(r.x), "=f"(r.y) : "l"(v));
    return r;
}

__device__ __forceinline__ void grid_barrier() {
    __threadfence();
    __syncthreads();
    if (threadIdx.x == 0) {
        unsigned gen = *(volatile unsigned*)&g_bar_gen;
        unsigned prev = atomicAdd(&g_bar_cnt, 1u);
        if (prev == NBLK - 1) {
            g_bar_cnt = 0;
            __threadfence();
            atomicAdd(&g_bar_gen, 1u);
        } else {
            while (*(volatile unsigned*)&g_bar_gen == gen) __nanosleep(32);
            __threadfence();
        }
    }
    __syncthreads();
}

// Pair-transpose a 64x64 row-major [k][j] matrix into (kp,jp) ulonglong2 tiles:
// Wp[kp*32+jp] = { (W[2kp][2jp], W[2kp+1][2jp]), (W[2kp][2jp+1], W[2kp+1][2jp+1]) }
__device__ __forceinline__ void stage_pairs(ull* dst, const float* __restrict__ W, int tid) {
    for (int idx = tid; idx < 1024; idx += BLKT) {
        int kp = idx >> 5, jp = idx & 31;
        const float* r0 = W + (2 * kp) * 64 + 2 * jp;
        const float* r1 = W + (2 * kp + 1) * 64 + 2 * jp;
        dst[2 * idx]     = packf2(r0[0], r1[0]);
        dst[2 * idx + 1] = packf2(r0[1], r1[1]);
    }
}

// k-pair matvec over all EBP edges (weights loaded once, double-buffered).
// hrow[e][kp] = (h[2kp], h[2kp+1]) of edge e, broadcast LDS.64.
// Thread owns output columns (2l, 2l+1); a0/a1 hold even/odd-k partials.
template <typename InitF, typename EmitF>
__device__ __forceinline__ void mv(const ulonglong2* __restrict__ Wp,
                                   const ull (&hrow)[EBP][32], int l,
                                   InitF init, EmitF emit) {
    ull a0[EBP], a1[EBP];
#pragma unroll
    for (int e = 0; e < EBP; e++) {
        float2 b = init(e);
        a0[e] = packf2(b.x, 0.f);
        a1[e] = packf2(b.y, 0.f);
    }
    ulonglong2 wq = Wp[l];   // kp = 0
#pragma unroll 8
    for (int kp = 0; kp < 32; kp++) {
        ulonglong2 wq_next = Wp[((kp < 31) ? (kp + 1) : 31) * 32 + l];
#pragma unroll
        for (int e = 0; e < EBP; e++) {
            ull hv = hrow[e][kp];
            a0[e] = ffma2(wq.x, hv, a0[e]);
            a1[e] = ffma2(wq.y, hv, a1[e]);
        }
        wq = wq_next;
    }
#pragma unroll
    for (int e = 0; e < EBP; e++) {
        float2 p = unpackf2(a0[e]), q = unpackf2(a1[e]);
        emit(e, make_float2(p.x + p.y, q.x + q.y));
    }
}

#define ZBURST()                                                          \
    {                                                                     \
        _Pragma("unroll") for (int j_ = 0; j_ < 8; j_++) {                \
            if (zi < ZTOT) __stcs(out4 + zi, z4);                         \
            zi += ZSTRIDE;                                                \
        }                                                                 \
    }

// ---------------- the single mega-kernel ----------------------------------
__global__ __launch_bounds__(BLKT, 2) void k_all(
    float* __restrict__ out,
    const float* __restrict__ v, const float* __restrict__ labels,
    const int* __restrict__ ei,
    const float* __restrict__ hxW1, const float* __restrict__ hxb1,
    const float* __restrict__ hxW2, const float* __restrict__ hxb2,
    const float* __restrict__ hyW1, const float* __restrict__ hyb1,
    const float* __restrict__ hyW2, const float* __restrict__ hyb2,
    const float* __restrict__ fxW1, const float* __restrict__ fxb1,
    const float* __restrict__ fxW2, const float* __restrict__ fxb2,
    const float* __restrict__ fyW1, const float* __restrict__ fyb1,
    const float* __restrict__ fyW2, const float* __restrict__ fyb2)
{
    extern __shared__ __align__(16) ull dsm[];   // 3 * 2048 ull = 48 KB
    ull* W2y = dsm;          // hyW2 then fyW2 (pair-transposed)
    ull* WCx = dsm + 2048;   // Cfx
    ull* W2x = dsm + 4096;   // fxW2
    __shared__ __align__(16) ull sH[WPB][EBP][32];   // 21 KB
    __shared__ float sB[6][64];   // 0:hyb1 1:hyb2 2:fyb1 3:fyb2 4:fxb1 5:fxb2

    int tid = threadIdx.x, w = tid >> 5, l = tid & 31;
    int gt = blockIdx.x * BLKT + tid;
    int wgid = blockIdx.x * WPB + w;
    float4* out4 = (float4*)out;
    const float4 z4 = make_float4(0.f, 0.f, 0.f, 0.f);
    unsigned zi = (unsigned)gt;

    // ================= P0: inputs -> scratch =================
    if (gt < N_NODES) {
        float row[8];
#pragma unroll
        for (int c = 0; c < 7; c++) row[c] = v[gt * 7 + c];
        row[7] = labels[gt];
#pragma unroll
        for (int c = 0; c < 8; c++) g_vc[gt * 8 + c] = row[c];
        if (row[7] > 0.5f) {
#pragma unroll
            for (int c = 0; c < 8; c++) g_goal[c] = row[c];
        }
    }
    if (gt < 4096) {
        float a = fxW1[gt];
        g_Afx[gt] = a + fxW1[4096 + gt];
        g_Bfx[gt] = fxW1[8192 + gt] - a;
        g_Cfx[gt] = fxW1[12288 + gt];
        float b = fyW1[gt];
        g_Afy[gt] = b + fyW1[4096 + gt];
        g_Bfy[gt] = fyW1[8192 + gt] - b;
    }
    if (gt < 512) {
        float c = hyW1[gt];
        g_Ahy[gt] = c + hyW1[512 + gt];
        g_Bhy[gt] = hyW1[1024 + gt] - c;
    }
    for (int i = gt; i < N_NODES * N_NODES; i += NTHREAD) g_winner[i] = -1;
    grid_barrier();

    // ================= P1: derived state =================
    if (gt < N_EDGES)
        atomicMax(&g_winner[ei[gt] * N_NODES + ei[N_EDGES + gt]], gt);
    for (int i = gt; i < N_NODES * E_DIM; i += NTHREAD) {
        int nn = i >> 6, j = i & 63;
        float s = 0.f, q = 0.f;
#pragma unroll
        for (int k = 0; k < 8; k++) {
            float vk = g_vc[nn * 8 + k];
            s += vk * g_Ahy[k * 64 + j];
            q += vk * g_Bhy[k * 64 + j];
        }
        __stcg(&g_Pv[i], s);
        __stcg(&g_Qv[i], q);
    }
    stage_pairs(W2y, hyW2, tid);
    stage_pairs(WCx, g_Cfx, tid);
    stage_pairs(W2x, fxW2, tid);
    if (tid < 64) {
        sB[0][tid] = hyb1[tid]; sB[1][tid] = hyb2[tid];
        sB[2][tid] = fyb1[tid]; sB[3][tid] = fyb2[tid];
        sB[4][tid] = fxb1[tid]; sB[5][tid] = fxb2[tid];
    }

    // node ownership: 2 warps per node; role 0 -> {Afx,Bfx}->PA,PB; role 1 -> {Afy,Bfy}->RA,RB
    int n = wgid >> 1;
    int role = wgid & 1;
    bool has_node = (n < N_NODES);
    float2 xv = make_float2(0.f, 0.f);

    // hx: both warps of the pair compute redundantly, result kept in registers
    if (has_node) {
        float* xs = (float*)&sH[w][0][0];   // 64+64 floats scratch in warp's region
        float* hs = xs + 64;
        {
            int g = l >> 3, r = l & 7;
            float vcv = g_vc[n * 8 + r];
            float gv  = g_goal[r];
            float dd  = vcv - gv;
            xs[l] = (g == 0) ? vcv : (g == 1) ? gv : (g == 2) ? dd : dd * dd;
        }
        __syncwarp();
        float2 acc = __ldg((const float2*)hxb1 + l);
#pragma unroll 4
        for (int k = 0; k < 32; k++) {
            float vk  = xs[k];
            float2 wv = __ldg((const float2*)hxW1 + k * 32 + l);
            acc.x += vk * wv.x; acc.y += vk * wv.y;
        }
        acc.x = fmaxf(acc.x, 0.f); acc.y = fmaxf(acc.y, 0.f);
        ((float2*)hs)[l] = acc;
        __syncwarp();
        float2 o = __ldg((const float2*)hxb2 + l);
#pragma unroll 4
        for (int k = 0; k < 64; k++) {
            float hk  = hs[k];
            float2 wv = __ldg((const float2*)hxW2 + k * 32 + l);
            o.x += hk * wv.x; o.y += hk * wv.y;
        }
        xv = o;
        __syncwarp();
    }

    // edge ownership (registers for the whole kernel)
    int ebase = wgid * EBP;
    int ec = N_EDGES - ebase;
    if (ec > EBP) ec = EBP;
    if (ec < 0) ec = 0;
    int src[EBP], tgt[EBP];
#pragma unroll
    for (int e = 0; e < EBP; e++) {
        int eg = (e < ec) ? (ebase + e) : 0;
        src[e] = __ldg(ei + eg);
        tgt[e] = __ldg(ei + N_EDGES + eg);
    }
    float2 yv[EBP];

    const float2* PA2 = (const float2*)g_PA;
    const float2* PB2 = (const float2*)g_PB;
    const float2* RA2 = (const float2*)g_RA;
    const float2* RB2 = (const float2*)g_RB;
    const float2* Pv2 = (const float2*)g_Pv;
    const float2* Qv2 = (const float2*)g_Qv;

    grid_barrier();

    // ================= main loop =================
    for (int t = 0; t <= N_LOOP; t++) {
        // ---- node phase ----
        if (t == 1) stage_pairs(W2y, fyW2, tid);   // swap hyW2 -> fyW2
        if (has_node) {
            if (t > 0) {
                // non-destructive read of agg buf[t&1] (both warps of the pair)
                const unsigned* ab = g_agg + (t & 1) * NAGG + n * 64 + 2 * l;
                unsigned a0 = __ldcg(ab);
                unsigned a1 = __ldcg(ab + 1);
                xv.x = fmaxf(xv.x, a0 ? decf(a0) : 0.f);
                xv.y = fmaxf(xv.y, a1 ? decf(a1) : 0.f);
            }
            // pre-zero the buffer edge(t) is about to write (role 0 only)
            if (role == 0 && t < N_LOOP)
                *(ull*)(g_agg + ((t + 1) & 1) * NAGG + n * 64 + 2 * l) = 0ull;

            float* xs = (float*)&sH[w][0][0];
            ((float2*)xs)[l] = xv;
            __syncwarp();
            const float2* M0 = (const float2*)(role ? g_Afy : g_Afx);
            const float2* M1 = (const float2*)(role ? g_Bfy : g_Bfx);
            float2 aA = make_float2(0.f, 0.f), aB = aA;
#pragma unroll 8
            for (int k = 0; k < 64; k++) {
                float xk = xs[k];
                float2 wa = __ldg(M0 + k * 32 + l);
                float2 wb = __ldg(M1 + k * 32 + l);
                aA.x += xk * wa.x; aA.y += xk * wa.y;
                aB.x += xk * wb.x; aB.y += xk * wb.y;
            }
            float2* D0 = (float2*)(role ? g_RA : g_PA);
            float2* D1 = (float2*)(role ? g_RB : g_PB);
            __stcg(D0 + n * 32 + l, aA);
            __stcg(D1 + n * 32 + l, aB);
            if (t == N_LOOP && role == 0)   // emit x tail straight from registers
                *(float2*)(out + XOFF + (size_t)n * 64 + 2 * l) = xv;
            __syncwarp();
        }
        ZBURST();                          // fill work during the short node phase
        grid_barrier();

        // ---- edge phase ----
        // layer 1 of hy (t==0) / fy: relu hidden pairs, lane l stages kp=l
        {
            float2 b1 = ((const float2*)sB[(t == 0) ? 0 : 2])[l];
            const float2* Tm = (t == 0) ? Pv2 : RA2;
            const float2* Sm = (t == 0) ? Qv2 : RB2;
#pragma unroll
            for (int e = 0; e < EBP; e++) {
                float2 a = __ldcg(Tm + tgt[e] * 32 + l);
                float2 b = __ldcg(Sm + src[e] * 32 + l);
                sH[w][e][l] = packf2(fmaxf(a.x + b.x + b1.x, 0.f),
                                     fmaxf(a.y + b.y + b1.y, 0.f));
            }
        }
        __syncwarp();
        ZBURST();

        // layer 2 of hy/fy -> yv
        {
            float2 b2 = ((const float2*)sB[(t == 0) ? 1 : 3])[l];
            mv((const ulonglong2*)W2y, sH[w], l,
               [&](int) { return b2; },
               [&](int e, float2 r) {
                   if (t == 0) yv[e] = r;
                   else { yv[e].x = fmaxf(yv[e].x, r.x); yv[e].y = fmaxf(yv[e].y, r.y); }
               });
        }
        ZBURST();

        if (t == N_LOOP) {
            // scatter winner rows straight from registers (zero-fill done @ t==9)
#pragma unroll
            for (int e = 0; e < EBP; e++) {
                if (e < ec) {
                    int key = src[e] * N_NODES + tgt[e];
                    if (__ldg(&g_winner[key]) == ebase + e)
                        __stcs((float2*)out + (size_t)key * 32 + l, yv[e]);
                }
            }
            break;
        }

        // stage y for fx layer 1
        __syncwarp();
#pragma unroll
        for (int e = 0; e < EBP; e++) sH[w][e][l] = packf2(yv[e].x, yv[e].y);
        __syncwarp();

        // fx layer 1: PA[src] + PB[tgt] + b1 + y @ Cfx, relu -> restage
        {
            float2 b1x = ((const float2*)sB[4])[l];
            mv((const ulonglong2*)WCx, sH[w], l,
               [&](int e) {
                   float2 pa = __ldcg(PA2 + src[e] * 32 + l);
                   float2 pb = __ldcg(PB2 + tgt[e] * 32 + l);
                   return make_float2(pa.x + pb.x + b1x.x, pa.y + pb.y + b1x.y);
               },
               [&](int e, float2 r) {
                   sH[w][e][l] = packf2(fmaxf(r.x, 0.f), fmaxf(r.y, 0.f));
               });
        }
        __syncwarp();
        ZBURST();

        // fx layer 2 + atomic max scatter into agg buf[(t+1)&1]
        {
            float2 b2x = ((const float2*)sB[5])[l];
            unsigned* abuf = g_agg + ((t + 1) & 1) * NAGG;
            mv((const ulonglong2*)W2x, sH[w], l,
               [&](int) { return b2x; },
               [&](int e, float2 r) {
                   if (e < ec) {
                       unsigned* ap = abuf + tgt[e] * 64 + 2 * l;
                       atomicMax(ap,     encf(r.x));
                       atomicMax(ap + 1, encf(r.y));
                   }
               });
        }
        ZBURST();

        if (t == N_LOOP - 1) {   // guarantee edge_feat zero-fill complete before scatter
            while (zi < ZTOT) { __stcs(out4 + zi, z4); zi += ZSTRIDE; }
        }
        grid_barrier();
    }
}

// ---------------- launch ---------------------------------------------------
extern "C" void kernel_launch(void* const* d_in, const int* in_sizes, int n_in,
                              void* d_out, int out_size) {
    const float* v      = (const float*)d_in[0];
    const float* labels = (const float*)d_in[1];
    const int*   ei     = (const int*)  d_in[4];
    const float* hxW1 = (const float*)d_in[6];
    const float* hxb1 = (const float*)d_in[7];
    const float* hxW2 = (const float*)d_in[8];
    const float* hxb2 = (const float*)d_in[9];
    const float* hyW1 = (const float*)d_in[10];
    const float* hyb1 = (const float*)d_in[11];
    const float* hyW2 = (const float*)d_in[12];
    const float* hyb2 = (const float*)d_in[13];
    const float* fxW1 = (const float*)d_in[14];
    const float* fxb1 = (const float*)d_in[15];
    const float* fxW2 = (const float*)d_in[16];
    const float* fxb2 = (const float*)d_in[17];
    const float* fyW1 = (const float*)d_in[18];
    const float* fyb1 = (const float*)d_in[19];
    const float* fyW2 = (const float*)d_in[20];
    const float* fyb2 = (const float*)d_in[21];
    float* out = (float*)d_out;

    const int DSM = 3 * 2048 * (int)sizeof(ull);   // 48 KB dynamic
    static bool attr_set = false;
    if (!attr_set) {
        cudaFuncSetAttribute(k_all, cudaFuncAttributeMaxDynamicSharedMemorySize, DSM);
        attr_set = true;
    }

    k_all<<<NBLK, BLKT, DSM>>>(out, v, labels, ei,
                               hxW1, hxb1, hxW2, hxb2,
                               hyW1, hyb1, hyW2, hyb2,
                               fxW1, fxb1, fxW2, fxb2,
                               fyW1, fyb1, fyW2, fyb2);
}